// round 14
// baseline (speedup 1.0000x reference)
#include <cuda_runtime.h>
#include <cuda_fp16.h>
#include <cstdint>

#define Bn 4
#define Tn 2048
#define En 1024
#define Hn 16
#define Dn 64
#define Kdim 1024
#define SC_LOG2 0.18033688f  // 0.125 * log2(e)

// ---------------- static device scratch (allocation-free) -------------------
__device__ __half g_a[Bn * Tn * En];         // activation fp16 (x, then y)
__device__ __half g_wq[3 * En * Kdim];       // w_qkv^T fp16 [N=3072][K]
__device__ __half g_wo[En * Kdim];           // w_out^T fp16
__device__ __half g_q[Bn * Hn * Tn * Dn];    // q fp16 PRE-SCALED [bh][t][d]
__device__ __half g_k[Bn * Hn * Tn * Dn];    // k fp16 [bh][t][d]
__device__ __half g_vt[Bn * Hn * Dn * Tn];   // v fp16 TRANSPOSED [bh][d][t]
__device__ int g_shift;

// ---------------- helpers (baseline PTX only: sm_80+ features) --------------
__device__ __forceinline__ void cp16(uint32_t s, const void* g) {
    asm volatile("cp.async.cg.shared.global [%0], [%1], 16;" :: "r"(s), "l"(g));
}
#define CP_COMMIT() asm volatile("cp.async.commit_group;" ::: "memory")
#define CP_WAIT(n) asm volatile("cp.async.wait_group %0;" :: "n"(n) : "memory")

__device__ __forceinline__ uint32_t smem_u32(const void* p) {
    uint32_t a;
    asm("{ .reg .u64 t; cvta.to.shared.u64 t, %1; cvt.u32.u64 %0, t; }"
        : "=r"(a) : "l"(p));
    return a;
}
__device__ __forceinline__ void mma16816(float* c, const uint32_t* a,
                                         const uint32_t* b) {
    asm volatile(
        "mma.sync.aligned.m16n8k16.row.col.f32.f16.f16.f32 "
        "{%0,%1,%2,%3}, {%4,%5,%6,%7}, {%8,%9}, {%0,%1,%2,%3};"
        : "+f"(c[0]), "+f"(c[1]), "+f"(c[2]), "+f"(c[3])
        : "r"(a[0]), "r"(a[1]), "r"(a[2]), "r"(a[3]), "r"(b[0]), "r"(b[1]));
}
#define LM4(r, addr)                                                       \
    asm volatile("ldmatrix.sync.aligned.m8n8.x4.shared.b16 "               \
                 "{%0,%1,%2,%3}, [%4];"                                    \
                 : "=r"((r)[0]), "=r"((r)[1]), "=r"((r)[2]), "=r"((r)[3])  \
                 : "r"(addr))
__device__ __forceinline__ float ex2f(float x) {
    float r;
    asm("ex2.approx.f32 %0, %1;" : "=f"(r) : "f"(x));
    return r;
}
__device__ __forceinline__ uint32_t hpack(float lo, float hi) {
    __half2 t = __floats2half2_rn(lo, hi);
    return *(uint32_t*)&t;
}

// ---------------- merged prep: x->fp16, weight transposes, ids detect -------
__global__ void __launch_bounds__(256)
prep_kernel(const float* __restrict__ x, const float* __restrict__ wqkv,
            const float* __restrict__ wout, const int* __restrict__ idsw) {
    __shared__ float tile[32][33];
    const int blk = blockIdx.x;
    const int tid = threadIdx.x;
    if (blk < 8192) {
        int i = blk * 256 + tid;
        float4 v = ((const float4*)x)[i];
        uint32_t* ph = (uint32_t*)g_a;
        ph[2 * i] = hpack(v.x, v.y);
        ph[2 * i + 1] = hpack(v.z, v.w);
        if (blk == 0 && tid == 0) {
            bool all0 = true;
            for (int j = 1; j < 64; j += 2) all0 = all0 && (idsw[j] == 0);
            g_shift = all0 ? 1 : 0;
        }
    } else {
        const float* W;
        __half* oh;
        int Nw, i;
        if (blk < 8192 + 3072) {
            i = blk - 8192; W = wqkv; oh = g_wq; Nw = 3 * En;
        } else {
            i = blk - 11264; W = wout; oh = g_wo; Nw = En;
        }
        const int nblk = Nw / 32;
        const int n0 = (i % nblk) * 32, k0 = (i / nblk) * 32;
        const int tx = tid & 31, ty = tid >> 5;
#pragma unroll
        for (int j = 0; j < 32; j += 8)
            tile[ty + j][tx] = W[(size_t)(k0 + ty + j) * Nw + n0 + tx];
        __syncthreads();
#pragma unroll
        for (int j = 0; j < 32; j += 8) {
            float a = tile[tx][ty + j];
            oh[(size_t)(n0 + ty + j) * Kdim + k0 + tx] = __float2half_rn(a);
        }
    }
}

// ---------------- HMMA fp16 GEMM: C[8192, Ntot] = A * W^T -------------------
// BM=128, BN=64, BK=64. 256 threads = 8 warps (4m x 2n), warp tile 32x32
// (acc = 32 regs -> 3 CTAs/SM = 24 warps for latency hiding).
template <int Ntot, bool QKV>
__global__ void __launch_bounds__(256, 3)
hmma_gemm(const float* __restrict__ bias, float* __restrict__ Cout) {
    constexpr int ROWB = 144;                   // bytes per smem row (72 half)
    constexpr int OFF_B = 18432;                // 128*144
    constexpr int STG = 27648;                  // (128+64)*144 bytes per stage
    constexpr int NK = Kdim / 64;               // 16
    extern __shared__ char smc[];
    const uint32_t smb = smem_u32(smc);

    const __half* Bg = QKV ? g_wq : g_wo;

    const int m0 = blockIdx.y * 128;
    const int n0 = blockIdx.x * 64;
    const int tid = threadIdx.x;
    const int wid = tid >> 5;
    const int lane = tid & 31;
    const int wm = wid >> 1;   // 0..3 (32-row slice)
    const int wn = wid & 1;    // 0..1 (32-col slice)
    const int lg = lane >> 2;
    const int lc = lane & 3;
    const int arow = (lane & 7) + ((lane >> 3) & 1) * 8;
    const int acol = ((lane >> 4) & 1) * 8;
    const int brow = (lane & 7) + ((lane >> 4) & 1) * 8;
    const int bcol = ((lane >> 3) & 1) * 8;

    float acc[2][4][4];
#pragma unroll
    for (int mi = 0; mi < 2; mi++)
#pragma unroll
        for (int ni = 0; ni < 4; ni++)
#pragma unroll
            for (int r = 0; r < 4; r++) acc[mi][ni][r] = 0.f;

    auto load_stage = [&](int kc, int s) {
        const int k0 = kc * 64;
        const uint32_t sb = smb + (uint32_t)s * STG;
#pragma unroll
        for (int c = tid; c < 1024; c += 256) {
            int row = c >> 3, col8 = (c & 7) * 8;
            cp16(sb + (uint32_t)(row * ROWB + col8 * 2),
                 g_a + (size_t)(m0 + row) * Kdim + k0 + col8);
            if (c < 512)
                cp16(sb + OFF_B + (uint32_t)(row * ROWB + col8 * 2),
                     Bg + (size_t)(n0 + row) * Kdim + k0 + col8);
        }
        CP_COMMIT();
    };

    load_stage(0, 0);

    int s = 0;
    for (int kc = 0; kc < NK; kc++) {
        CP_WAIT(0);
        __syncthreads();
        if (kc + 1 < NK) load_stage(kc + 1, s ^ 1);

        const uint32_t sb = smb + (uint32_t)s * STG;
        const uint32_t aB = sb + (uint32_t)((wm * 32 + arow) * ROWB + acol * 2);
        const uint32_t bB = sb + OFF_B +
                            (uint32_t)((wn * 32 + brow) * ROWB + bcol * 2);
#pragma unroll
        for (int ks = 0; ks < 4; ks++) {
            uint32_t ah[2][4];
#pragma unroll
            for (int mi = 0; mi < 2; mi++)
                LM4(ah[mi], aB + mi * 16 * ROWB + ks * 32);
#pragma unroll
            for (int nj = 0; nj < 2; nj++) {
                uint32_t b[4];
                LM4(b, bB + nj * 16 * ROWB + ks * 32);
#pragma unroll
                for (int mi = 0; mi < 2; mi++) {
                    mma16816(acc[mi][2 * nj], ah[mi], b);
                    mma16816(acc[mi][2 * nj + 1], ah[mi], b + 2);
                }
            }
        }
        s ^= 1;
    }

    if (QKV) {
        const int which = n0 >> 10;
        const int b = m0 >> 11;
        const int h = (n0 & 1023) >> 6;  // one head per CTA (BN=64)
        if (which < 2) {
            __half* dst = which == 0 ? g_q : g_k;
            const float sc = which == 0 ? SC_LOG2 : 1.0f;  // pre-scale Q
#pragma unroll
            for (int mi = 0; mi < 2; mi++)
#pragma unroll
                for (int ni = 0; ni < 4; ni++)
#pragma unroll
                    for (int half = 0; half < 2; half++) {
                        int m = m0 + wm * 32 + mi * 16 + lg + half * 8;
                        int t = m & (Tn - 1);
                        int d = wn * 32 + ni * 8 + lc * 2;
                        size_t off = (((size_t)(b * Hn + h)) * Tn + t) * Dn + d;
                        *(uint32_t*)&dst[off] =
                            hpack(acc[mi][ni][half * 2] * sc,
                                  acc[mi][ni][half * 2 + 1] * sc);
                    }
        } else {
            // V: fp16, transposed through smem -> [bh][d][t]
            __syncthreads();
            __half* sV = (__half*)smc;  // [64 d][136 t]
#pragma unroll
            for (int mi = 0; mi < 2; mi++)
#pragma unroll
                for (int ni = 0; ni < 4; ni++)
#pragma unroll
                    for (int half = 0; half < 2; half++) {
                        int tl = wm * 32 + mi * 16 + lg + half * 8;
                        int col = wn * 32 + ni * 8 + lc * 2;
                        sV[col * 136 + tl] =
                            __float2half_rn(acc[mi][ni][half * 2]);
                        sV[(col + 1) * 136 + tl] =
                            __float2half_rn(acc[mi][ni][half * 2 + 1]);
                    }
            __syncthreads();
            const int t0 = m0 & (Tn - 1);
#pragma unroll
            for (int c = tid; c < 1024; c += 256) {
                int col = c >> 4, t8 = (c & 15) * 8;
                uint4 vh = *(uint4*)&sV[col * 136 + t8];
                size_t off = (((size_t)(b * Hn + h)) * Dn + col) * Tn + t0 + t8;
                *(uint4*)&g_vt[off] = vh;
            }
        }
    } else {
#pragma unroll
        for (int mi = 0; mi < 2; mi++)
#pragma unroll
            for (int ni = 0; ni < 4; ni++) {
                int r0 = m0 + wm * 32 + mi * 16 + lg;
                int n = n0 + wn * 32 + ni * 8 + lc * 2;
#pragma unroll
                for (int half = 0; half < 2; half++) {
                    int m = r0 + half * 8;
                    float2 v = make_float2(acc[mi][ni][half * 2],
                                           acc[mi][ni][half * 2 + 1]);
                    v.x += bias[n];
                    v.y += bias[n + 1];
                    *(float2*)&Cout[(size_t)m * Ntot + n] = v;
                }
            }
    }
}

// ---------------- flash attention: HMMA fp16 single, FA-2 style -------------
// UNCHANGED (frozen) from the passing round-13 kernel.
#define SSTG 18432       // stage base (after the full Q tile: 128 x 144 B)
#define SSTGSZ 18432     // per stage: K@0 (9216), V@9216
#define SKEEP 55296      // float[2][64]
#define FLASH_SMEM 55808

__global__ void __launch_bounds__(256, 2)
flash_kernel(const int* __restrict__ idsw) {
    extern __shared__ char smc[];
    const uint32_t smb = smem_u32(smc);

    const int qt = (int)gridDim.x - 1 - (int)blockIdx.x;
    const int bh = blockIdx.y;
    const int b = bh >> 4;
    const int h = bh & 15;
    const int qbase = qt * 128;
    const int tid = threadIdx.x;
    const int wm = tid >> 5;
    const int lane = tid & 31;
    const int lg = lane >> 2;
    const int lc = lane & 3;
    const int shift = g_shift;
    const int nt = 2 * qt + 2;

    const int qrow = (lane & 7) + ((lane >> 3) & 1) * 8;
    const int qcol = ((lane >> 4) & 1) * 8;
    const int krow = (lane & 7) + ((lane >> 4) & 1) * 8;
    const int kcol = ((lane >> 3) & 1) * 8;

    const uint32_t aq = smb + (uint32_t)((wm * 16 + qrow) * 144 + qcol * 2);

    auto load_kv = [&](int kt, int s) {
        const int kv0 = kt * 64;
        const uint32_t sb = smb + SSTG + (uint32_t)s * SSTGSZ;
#pragma unroll
        for (int ch = tid; ch < 512; ch += 256) {
            int r = ch >> 3, c8 = (ch & 7) << 3;
            uint32_t so = sb + (uint32_t)(r * 144 + c8 * 2);
            cp16(so, g_k + ((size_t)bh * Tn + kv0 + r) * Dn + c8);
            cp16(so + 9216, g_vt + ((size_t)bh * Dn + r) * Tn + kv0 + c8);
        }
        if (tid < 64) {
            size_t w = ((size_t)(b * Tn + kv0 + tid)) << shift;
            float ka = (idsw[w] != 0) ? 0.f : -1e30f;
            *(float*)(smc + SKEEP + s * 256 + tid * 4) = ka;
        }
        CP_COMMIT();
    };

#pragma unroll
    for (int ch = tid; ch < 1024; ch += 256) {
        int r = ch >> 3, c8 = (ch & 7) << 3;
        cp16(smb + (uint32_t)(r * 144 + c8 * 2),
             g_q + ((size_t)bh * Tn + qbase + r) * Dn + c8);
    }
    load_kv(0, 0);

    float o[8][4];
#pragma unroll
    for (int i = 0; i < 8; i++)
#pragma unroll
        for (int j = 0; j < 4; j++) o[i][j] = 0.f;
    float m0r = -1e30f, m1r = -1e30f, l0r = 0.f, l1r = 0.f;

    const int r0gl = qbase + wm * 16 + lg;
    const int r1gl = r0gl + 8;

    for (int kt = 0; kt < nt; kt++) {
        const int s = kt & 1;
        if (kt + 1 < nt) {
            load_kv(kt + 1, s ^ 1);
            CP_WAIT(1);
        } else {
            CP_WAIT(0);
        }
        __syncthreads();

        const uint32_t stg = smb + SSTG + (uint32_t)s * SSTGSZ;
        const int kv0 = kt * 64;

        float c[8][4];
#pragma unroll
        for (int i = 0; i < 8; i++)
#pragma unroll
            for (int j = 0; j < 4; j++) c[i][j] = 0.f;

#pragma unroll
        for (int ks = 0; ks < 4; ks++) {
            uint32_t ah[4];
            LM4(ah, aq + ks * 32);
#pragma unroll
            for (int pi = 0; pi < 4; pi++) {
                uint32_t kb[4];
                LM4(kb, stg + (uint32_t)((pi * 16 + krow) * 144 + kcol * 2) +
                            ks * 32);
                mma16816(c[2 * pi], ah, kb);
                mma16816(c[2 * pi + 1], ah, kb + 2);
            }
        }

        const float* keepf = (const float*)(smc + SKEEP + s * 256);
        float mx0 = -1e30f, mx1 = -1e30f;
        if (kv0 + 63 <= qbase + wm * 16) {
#pragma unroll
            for (int ni = 0; ni < 8; ni++) {
                float2 kp = *(const float2*)&keepf[ni * 8 + 2 * lc];
                float t0 = c[ni][0] + kp.x;
                float t1 = c[ni][1] + kp.y;
                float t2 = c[ni][2] + kp.x;
                float t3 = c[ni][3] + kp.y;
                c[ni][0] = t0; c[ni][1] = t1; c[ni][2] = t2; c[ni][3] = t3;
                mx0 = fmaxf(mx0, fmaxf(t0, t1));
                mx1 = fmaxf(mx1, fmaxf(t2, t3));
            }
        } else {
#pragma unroll
            for (int ni = 0; ni < 8; ni++) {
                int cg = kv0 + ni * 8 + 2 * lc;
                float2 kp = *(const float2*)&keepf[ni * 8 + 2 * lc];
                float t0 = c[ni][0] + kp.x;
                float t1 = c[ni][1] + kp.y;
                float t2 = c[ni][2] + kp.x;
                float t3 = c[ni][3] + kp.y;
                if (cg > r0gl) t0 = -1e30f;
                if (cg + 1 > r0gl) t1 = -1e30f;
                if (cg > r1gl) t2 = -1e30f;
                if (cg + 1 > r1gl) t3 = -1e30f;
                c[ni][0] = t0; c[ni][1] = t1; c[ni][2] = t2; c[ni][3] = t3;
                mx0 = fmaxf(mx0, fmaxf(t0, t1));
                mx1 = fmaxf(mx1, fmaxf(t2, t3));
            }
        }
        mx0 = fmaxf(mx0, __shfl_xor_sync(0xffffffffu, mx0, 1));
        mx0 = fmaxf(mx0, __shfl_xor_sync(0xffffffffu, mx0, 2));
        mx1 = fmaxf(mx1, __shfl_xor_sync(0xffffffffu, mx1, 1));
        mx1 = fmaxf(mx1, __shfl_xor_sync(0xffffffffu, mx1, 2));
        float mn0 = fmaxf(m0r, mx0), mn1 = fmaxf(m1r, mx1);
        float al0 = ex2f(m0r - mn0), al1 = ex2f(m1r - mn1);
        float ls0 = 0.f, ls1 = 0.f;
#pragma unroll
        for (int ni = 0; ni < 8; ni++) {
            float p0 = ex2f(c[ni][0] - mn0);
            float p1 = ex2f(c[ni][1] - mn0);
            float p2 = ex2f(c[ni][2] - mn1);
            float p3 = ex2f(c[ni][3] - mn1);
            c[ni][0] = p0; c[ni][1] = p1; c[ni][2] = p2; c[ni][3] = p3;
            ls0 += p0 + p1;
            ls1 += p2 + p3;
        }
        ls0 += __shfl_xor_sync(0xffffffffu, ls0, 1);
        ls0 += __shfl_xor_sync(0xffffffffu, ls0, 2);
        ls1 += __shfl_xor_sync(0xffffffffu, ls1, 1);
        ls1 += __shfl_xor_sync(0xffffffffu, ls1, 2);
        l0r = l0r * al0 + ls0;
        l1r = l1r * al1 + ls1;
        m0r = mn0;
        m1r = mn1;
#pragma unroll
        for (int nd = 0; nd < 8; nd++) {
            o[nd][0] *= al0; o[nd][1] *= al0;
            o[nd][2] *= al1; o[nd][3] *= al1;
        }

#pragma unroll
        for (int ks = 0; ks < 4; ks++) {
            uint32_t pah[4];
#pragma unroll
            for (int u = 0; u < 2; u++) {
                pah[2 * u] = hpack(c[2 * ks + u][0], c[2 * ks + u][1]);
                pah[2 * u + 1] = hpack(c[2 * ks + u][2], c[2 * ks + u][3]);
            }
#pragma unroll
            for (int pd = 0; pd < 4; pd++) {
                uint32_t vb[4];
                LM4(vb, stg + 9216 +
                            (uint32_t)((pd * 16 + krow) * 144 + kcol * 2) +
                            ks * 32);
                mma16816(o[2 * pd], pah, vb);
                mma16816(o[2 * pd + 1], pah, vb + 2);
            }
        }
        __syncthreads();
    }

    const float i0 = 1.f / l0r, i1 = 1.f / l1r;
    const size_t row0 = (size_t)b * Tn + qbase + wm * 16 + lg;
    const size_t row1 = row0 + 8;
#pragma unroll
    for (int nd = 0; nd < 8; nd++) {
        int col = h * Dn + nd * 8 + 2 * lc;
        *(uint32_t*)&g_a[row0 * En + col] = hpack(o[nd][0] * i0, o[nd][1] * i0);
        *(uint32_t*)&g_a[row1 * En + col] = hpack(o[nd][2] * i1, o[nd][3] * i1);
    }
}

// ---------------------------------------------------------------------------
extern "C" void kernel_launch(void* const* d_in, const int* in_sizes, int n_in,
                              void* d_out, int out_size) {
    (void)in_sizes; (void)n_in; (void)out_size;
    const float* x = (const float*)d_in[0];
    const int* idsw = (const int*)d_in[1];
    const float* w_qkv = (const float*)d_in[2];
    const float* w_out = (const float*)d_in[3];
    const float* b_out = (const float*)d_in[4];
    float* out = (float*)d_out;

    // merged prep: x->fp16 + ids detect + weight transposes (one launch)
    prep_kernel<<<12288, 256>>>(x, w_qkv, w_out, idsw);

    const int gsmem = 2 * 27648;  // 55296 B -> 3 CTAs/SM (24 warps)
    cudaFuncSetAttribute(hmma_gemm<3 * En, true>,
                         cudaFuncAttributeMaxDynamicSharedMemorySize, gsmem);
    cudaFuncSetAttribute(hmma_gemm<En, false>,
                         cudaFuncAttributeMaxDynamicSharedMemorySize, gsmem);

    // 1) QKV projection -> q (pre-scaled), k ([bh][t][d]) + v^T ([bh][d][t])
    dim3 g1(3 * En / 64, Bn * Tn / 128);  // (48, 64)
    hmma_gemm<3 * En, true><<<g1, 256, gsmem>>>(nullptr, nullptr);

    // 2) flash attention (fp16 single) -> y fp16 into g_a
    cudaFuncSetAttribute(flash_kernel,
                         cudaFuncAttributeMaxDynamicSharedMemorySize, FLASH_SMEM);
    dim3 g2(Tn / 128, Bn * Hn);  // (16, 64)
    flash_kernel<<<g2, 256, FLASH_SMEM>>>(idsw);

    // 3) output projection + bias
    dim3 g3(En / 64, Bn * Tn / 128);  // (16, 64)
    hmma_gemm<En, false><<<g3, 256, gsmem>>>(b_out, out);
}

// round 15
// speedup vs baseline: 1.0492x; 1.0492x over previous
#include <cuda_runtime.h>
#include <cuda_fp16.h>
#include <cstdint>

#define Bn 4
#define Tn 2048
#define En 1024
#define Hn 16
#define Dn 64
#define Kdim 1024
#define SC_LOG2 0.18033688f  // 0.125 * log2(e)

// ---------------- static device scratch (allocation-free) -------------------
__device__ __half g_a[Bn * Tn * En];         // activation fp16 (x, then y)
__device__ __half g_wq[3 * En * Kdim];       // w_qkv^T fp16 [N=3072][K]
__device__ __half g_wo[En * Kdim];           // w_out^T fp16
__device__ __half g_q[Bn * Hn * Tn * Dn];    // q fp16 PRE-SCALED [bh][t][d]
__device__ __half g_k[Bn * Hn * Tn * Dn];    // k fp16 [bh][t][d]
__device__ __half g_vt[Bn * Hn * Dn * Tn];   // v fp16 TRANSPOSED [bh][d][t]
__device__ int g_shift;

// ---------------- helpers (baseline PTX only: sm_80+ features) --------------
__device__ __forceinline__ void cp16(uint32_t s, const void* g) {
    asm volatile("cp.async.cg.shared.global [%0], [%1], 16;" :: "r"(s), "l"(g));
}
#define CP_COMMIT() asm volatile("cp.async.commit_group;" ::: "memory")
#define CP_WAIT(n) asm volatile("cp.async.wait_group %0;" :: "n"(n) : "memory")

__device__ __forceinline__ uint32_t smem_u32(const void* p) {
    uint32_t a;
    asm("{ .reg .u64 t; cvta.to.shared.u64 t, %1; cvt.u32.u64 %0, t; }"
        : "=r"(a) : "l"(p));
    return a;
}
__device__ __forceinline__ void mma16816(float* c, const uint32_t* a,
                                         const uint32_t* b) {
    asm volatile(
        "mma.sync.aligned.m16n8k16.row.col.f32.f16.f16.f32 "
        "{%0,%1,%2,%3}, {%4,%5,%6,%7}, {%8,%9}, {%0,%1,%2,%3};"
        : "+f"(c[0]), "+f"(c[1]), "+f"(c[2]), "+f"(c[3])
        : "r"(a[0]), "r"(a[1]), "r"(a[2]), "r"(a[3]), "r"(b[0]), "r"(b[1]));
}
#define LM4(r, addr)                                                       \
    asm volatile("ldmatrix.sync.aligned.m8n8.x4.shared.b16 "               \
                 "{%0,%1,%2,%3}, [%4];"                                    \
                 : "=r"((r)[0]), "=r"((r)[1]), "=r"((r)[2]), "=r"((r)[3])  \
                 : "r"(addr))
__device__ __forceinline__ float ex2f(float x) {
    float r;
    asm("ex2.approx.f32 %0, %1;" : "=f"(r) : "f"(x));
    return r;
}
__device__ __forceinline__ uint32_t hpack(float lo, float hi) {
    __half2 t = __floats2half2_rn(lo, hi);
    return *(uint32_t*)&t;
}

// ---------------- merged prep: x->fp16 (MLP=4), transposes, ids detect ------
// blocks [0, 2048): split x, 4 strided float4s per thread (coalesced, MLP=4).
// blocks [2048, 5120): w_qkv transpose. blocks [5120, 6144): w_out transpose.
__global__ void __launch_bounds__(256)
prep_kernel(const float* __restrict__ x, const float* __restrict__ wqkv,
            const float* __restrict__ wout, const int* __restrict__ idsw) {
    __shared__ float tile[32][33];
    const int blk = blockIdx.x;
    const int tid = threadIdx.x;
    if (blk < 2048) {
        const int base = blk * 256 + tid;  // 0..524287
        const float4* src4 = (const float4*)x;
        uint32_t* ph = (uint32_t*)g_a;
#pragma unroll
        for (int j = 0; j < 4; j++) {
            int i = base + j * 524288;
            float4 v = src4[i];
            ph[2 * i] = hpack(v.x, v.y);
            ph[2 * i + 1] = hpack(v.z, v.w);
        }
        if (blk == 0 && tid == 0) {
            bool all0 = true;
            for (int j = 1; j < 64; j += 2) all0 = all0 && (idsw[j] == 0);
            g_shift = all0 ? 1 : 0;
        }
    } else {
        const float* W;
        __half* oh;
        int Nw, i;
        if (blk < 2048 + 3072) {
            i = blk - 2048; W = wqkv; oh = g_wq; Nw = 3 * En;
        } else {
            i = blk - 5120; W = wout; oh = g_wo; Nw = En;
        }
        const int nblk = Nw / 32;
        const int n0 = (i % nblk) * 32, k0 = (i / nblk) * 32;
        const int tx = tid & 31, ty = tid >> 5;
#pragma unroll
        for (int j = 0; j < 32; j += 8)
            tile[ty + j][tx] = W[(size_t)(k0 + ty + j) * Nw + n0 + tx];
        __syncthreads();
#pragma unroll
        for (int j = 0; j < 32; j += 8) {
            float a = tile[tx][ty + j];
            oh[(size_t)(n0 + ty + j) * Kdim + k0 + tx] = __float2half_rn(a);
        }
    }
}

// ---------------- HMMA fp16 GEMM: C[8192, Ntot] = A * W^T -------------------
// Round-13 config (best): BM=128, BN=64, BK=64. 128 threads = 4 warps
// (4m x 1n), warp tile 32x64. 2-stage cp.async, ldmatrix, 4 CTAs/SM.
template <int Ntot, bool QKV>
__global__ void __launch_bounds__(128, 4)
hmma_gemm(const float* __restrict__ bias, float* __restrict__ Cout) {
    constexpr int ROWB = 144;                   // bytes per smem row (72 half)
    constexpr int OFF_B = 18432;                // 128*144
    constexpr int STG = 27648;                  // (128+64)*144 bytes per stage
    constexpr int NK = Kdim / 64;               // 16
    extern __shared__ char smc[];
    const uint32_t smb = smem_u32(smc);

    const __half* Bg = QKV ? g_wq : g_wo;

    const int m0 = blockIdx.y * 128;
    const int n0 = blockIdx.x * 64;
    const int tid = threadIdx.x;
    const int wm = tid >> 5;   // 0..3 (warp = m slice)
    const int lane = tid & 31;
    const int lg = lane >> 2;
    const int lc = lane & 3;
    const int arow = (lane & 7) + ((lane >> 3) & 1) * 8;
    const int acol = ((lane >> 4) & 1) * 8;
    const int brow = (lane & 7) + ((lane >> 4) & 1) * 8;
    const int bcol = ((lane >> 3) & 1) * 8;

    float acc[2][8][4];
#pragma unroll
    for (int mi = 0; mi < 2; mi++)
#pragma unroll
        for (int ni = 0; ni < 8; ni++)
#pragma unroll
            for (int r = 0; r < 4; r++) acc[mi][ni][r] = 0.f;

    auto load_stage = [&](int kc, int s) {
        const int k0 = kc * 64;
        const uint32_t sb = smb + (uint32_t)s * STG;
#pragma unroll
        for (int c = tid; c < 1024; c += 128) {
            int row = c >> 3, col8 = (c & 7) * 8;
            cp16(sb + (uint32_t)(row * ROWB + col8 * 2),
                 g_a + (size_t)(m0 + row) * Kdim + k0 + col8);
            if (c < 512)
                cp16(sb + OFF_B + (uint32_t)(row * ROWB + col8 * 2),
                     Bg + (size_t)(n0 + row) * Kdim + k0 + col8);
        }
        CP_COMMIT();
    };

    load_stage(0, 0);

    int s = 0;
    for (int kc = 0; kc < NK; kc++) {
        CP_WAIT(0);
        __syncthreads();
        if (kc + 1 < NK) load_stage(kc + 1, s ^ 1);

        const uint32_t sb = smb + (uint32_t)s * STG;
        const uint32_t aB = sb + (uint32_t)((wm * 32 + arow) * ROWB + acol * 2);
        const uint32_t bB = sb + OFF_B + (uint32_t)(brow * ROWB + bcol * 2);
#pragma unroll
        for (int ks = 0; ks < 4; ks++) {
            uint32_t ah[2][4];
#pragma unroll
            for (int mi = 0; mi < 2; mi++)
                LM4(ah[mi], aB + mi * 16 * ROWB + ks * 32);
#pragma unroll
            for (int nj = 0; nj < 4; nj++) {
                uint32_t b[4];
                LM4(b, bB + nj * 16 * ROWB + ks * 32);
#pragma unroll
                for (int mi = 0; mi < 2; mi++) {
                    mma16816(acc[mi][2 * nj], ah[mi], b);
                    mma16816(acc[mi][2 * nj + 1], ah[mi], b + 2);
                }
            }
        }
        s ^= 1;
    }

    if (QKV) {
        const int which = n0 >> 10;
        const int b = m0 >> 11;
        const int h = (n0 & 1023) >> 6;  // one head per CTA (BN=64)
        if (which < 2) {
            __half* dst = which == 0 ? g_q : g_k;
            const float sc = which == 0 ? SC_LOG2 : 1.0f;  // pre-scale Q
#pragma unroll
            for (int mi = 0; mi < 2; mi++)
#pragma unroll
                for (int ni = 0; ni < 8; ni++)
#pragma unroll
                    for (int half = 0; half < 2; half++) {
                        int m = m0 + wm * 32 + mi * 16 + lg + half * 8;
                        int t = m & (Tn - 1);
                        int d = ni * 8 + lc * 2;
                        size_t off = (((size_t)(b * Hn + h)) * Tn + t) * Dn + d;
                        *(uint32_t*)&dst[off] =
                            hpack(acc[mi][ni][half * 2] * sc,
                                  acc[mi][ni][half * 2 + 1] * sc);
                    }
        } else {
            // V: fp16, transposed through smem -> [bh][d][t]
            __syncthreads();
            __half* sV = (__half*)smc;  // [64 d][136]
#pragma unroll
            for (int mi = 0; mi < 2; mi++)
#pragma unroll
                for (int ni = 0; ni < 8; ni++)
#pragma unroll
                    for (int half = 0; half < 2; half++) {
                        int tl = wm * 32 + mi * 16 + lg + half * 8;
                        int col = ni * 8 + lc * 2;
                        sV[col * 136 + tl] =
                            __float2half_rn(acc[mi][ni][half * 2]);
                        sV[(col + 1) * 136 + tl] =
                            __float2half_rn(acc[mi][ni][half * 2 + 1]);
                    }
            __syncthreads();
            const int t0 = m0 & (Tn - 1);
#pragma unroll
            for (int c = tid; c < 1024; c += 128) {
                int col = c >> 4, t8 = (c & 15) * 8;
                uint4 vh = *(uint4*)&sV[col * 136 + t8];
                size_t off = (((size_t)(b * Hn + h)) * Dn + col) * Tn + t0 + t8;
                *(uint4*)&g_vt[off] = vh;
            }
        }
    } else {
#pragma unroll
        for (int mi = 0; mi < 2; mi++)
#pragma unroll
            for (int ni = 0; ni < 8; ni++) {
                int r0 = m0 + wm * 32 + mi * 16 + lg;
                int n = n0 + ni * 8 + lc * 2;
#pragma unroll
                for (int half = 0; half < 2; half++) {
                    int m = r0 + half * 8;
                    float2 v = make_float2(acc[mi][ni][half * 2],
                                           acc[mi][ni][half * 2 + 1]);
                    v.x += bias[n];
                    v.y += bias[n + 1];
                    *(float2*)&Cout[(size_t)m * Ntot + n] = v;
                }
            }
    }
}

// ---------------- flash attention: HMMA fp16 single, FA-2 style -------------
// UNCHANGED (frozen) from the passing round-13 kernel.
#define SSTG 18432       // stage base (after the full Q tile: 128 x 144 B)
#define SSTGSZ 18432     // per stage: K@0 (9216), V@9216
#define SKEEP 55296      // float[2][64]
#define FLASH_SMEM 55808

__global__ void __launch_bounds__(256, 2)
flash_kernel(const int* __restrict__ idsw) {
    extern __shared__ char smc[];
    const uint32_t smb = smem_u32(smc);

    const int qt = (int)gridDim.x - 1 - (int)blockIdx.x;
    const int bh = blockIdx.y;
    const int b = bh >> 4;
    const int h = bh & 15;
    const int qbase = qt * 128;
    const int tid = threadIdx.x;
    const int wm = tid >> 5;
    const int lane = tid & 31;
    const int lg = lane >> 2;
    const int lc = lane & 3;
    const int shift = g_shift;
    const int nt = 2 * qt + 2;

    const int qrow = (lane & 7) + ((lane >> 3) & 1) * 8;
    const int qcol = ((lane >> 4) & 1) * 8;
    const int krow = (lane & 7) + ((lane >> 4) & 1) * 8;
    const int kcol = ((lane >> 3) & 1) * 8;

    const uint32_t aq = smb + (uint32_t)((wm * 16 + qrow) * 144 + qcol * 2);

    auto load_kv = [&](int kt, int s) {
        const int kv0 = kt * 64;
        const uint32_t sb = smb + SSTG + (uint32_t)s * SSTGSZ;
#pragma unroll
        for (int ch = tid; ch < 512; ch += 256) {
            int r = ch >> 3, c8 = (ch & 7) << 3;
            uint32_t so = sb + (uint32_t)(r * 144 + c8 * 2);
            cp16(so, g_k + ((size_t)bh * Tn + kv0 + r) * Dn + c8);
            cp16(so + 9216, g_vt + ((size_t)bh * Dn + r) * Tn + kv0 + c8);
        }
        if (tid < 64) {
            size_t w = ((size_t)(b * Tn + kv0 + tid)) << shift;
            float ka = (idsw[w] != 0) ? 0.f : -1e30f;
            *(float*)(smc + SKEEP + s * 256 + tid * 4) = ka;
        }
        CP_COMMIT();
    };

#pragma unroll
    for (int ch = tid; ch < 1024; ch += 256) {
        int r = ch >> 3, c8 = (ch & 7) << 3;
        cp16(smb + (uint32_t)(r * 144 + c8 * 2),
             g_q + ((size_t)bh * Tn + qbase + r) * Dn + c8);
    }
    load_kv(0, 0);

    float o[8][4];
#pragma unroll
    for (int i = 0; i < 8; i++)
#pragma unroll
        for (int j = 0; j < 4; j++) o[i][j] = 0.f;
    float m0r = -1e30f, m1r = -1e30f, l0r = 0.f, l1r = 0.f;

    const int r0gl = qbase + wm * 16 + lg;
    const int r1gl = r0gl + 8;

    for (int kt = 0; kt < nt; kt++) {
        const int s = kt & 1;
        if (kt + 1 < nt) {
            load_kv(kt + 1, s ^ 1);
            CP_WAIT(1);
        } else {
            CP_WAIT(0);
        }
        __syncthreads();

        const uint32_t stg = smb + SSTG + (uint32_t)s * SSTGSZ;
        const int kv0 = kt * 64;

        float c[8][4];
#pragma unroll
        for (int i = 0; i < 8; i++)
#pragma unroll
            for (int j = 0; j < 4; j++) c[i][j] = 0.f;

#pragma unroll
        for (int ks = 0; ks < 4; ks++) {
            uint32_t ah[4];
            LM4(ah, aq + ks * 32);
#pragma unroll
            for (int pi = 0; pi < 4; pi++) {
                uint32_t kb[4];
                LM4(kb, stg + (uint32_t)((pi * 16 + krow) * 144 + kcol * 2) +
                            ks * 32);
                mma16816(c[2 * pi], ah, kb);
                mma16816(c[2 * pi + 1], ah, kb + 2);
            }
        }

        const float* keepf = (const float*)(smc + SKEEP + s * 256);
        float mx0 = -1e30f, mx1 = -1e30f;
        if (kv0 + 63 <= qbase + wm * 16) {
#pragma unroll
            for (int ni = 0; ni < 8; ni++) {
                float2 kp = *(const float2*)&keepf[ni * 8 + 2 * lc];
                float t0 = c[ni][0] + kp.x;
                float t1 = c[ni][1] + kp.y;
                float t2 = c[ni][2] + kp.x;
                float t3 = c[ni][3] + kp.y;
                c[ni][0] = t0; c[ni][1] = t1; c[ni][2] = t2; c[ni][3] = t3;
                mx0 = fmaxf(mx0, fmaxf(t0, t1));
                mx1 = fmaxf(mx1, fmaxf(t2, t3));
            }
        } else {
#pragma unroll
            for (int ni = 0; ni < 8; ni++) {
                int cg = kv0 + ni * 8 + 2 * lc;
                float2 kp = *(const float2*)&keepf[ni * 8 + 2 * lc];
                float t0 = c[ni][0] + kp.x;
                float t1 = c[ni][1] + kp.y;
                float t2 = c[ni][2] + kp.x;
                float t3 = c[ni][3] + kp.y;
                if (cg > r0gl) t0 = -1e30f;
                if (cg + 1 > r0gl) t1 = -1e30f;
                if (cg > r1gl) t2 = -1e30f;
                if (cg + 1 > r1gl) t3 = -1e30f;
                c[ni][0] = t0; c[ni][1] = t1; c[ni][2] = t2; c[ni][3] = t3;
                mx0 = fmaxf(mx0, fmaxf(t0, t1));
                mx1 = fmaxf(mx1, fmaxf(t2, t3));
            }
        }
        mx0 = fmaxf(mx0, __shfl_xor_sync(0xffffffffu, mx0, 1));
        mx0 = fmaxf(mx0, __shfl_xor_sync(0xffffffffu, mx0, 2));
        mx1 = fmaxf(mx1, __shfl_xor_sync(0xffffffffu, mx1, 1));
        mx1 = fmaxf(mx1, __shfl_xor_sync(0xffffffffu, mx1, 2));
        float mn0 = fmaxf(m0r, mx0), mn1 = fmaxf(m1r, mx1);
        float al0 = ex2f(m0r - mn0), al1 = ex2f(m1r - mn1);
        float ls0 = 0.f, ls1 = 0.f;
#pragma unroll
        for (int ni = 0; ni < 8; ni++) {
            float p0 = ex2f(c[ni][0] - mn0);
            float p1 = ex2f(c[ni][1] - mn0);
            float p2 = ex2f(c[ni][2] - mn1);
            float p3 = ex2f(c[ni][3] - mn1);
            c[ni][0] = p0; c[ni][1] = p1; c[ni][2] = p2; c[ni][3] = p3;
            ls0 += p0 + p1;
            ls1 += p2 + p3;
        }
        ls0 += __shfl_xor_sync(0xffffffffu, ls0, 1);
        ls0 += __shfl_xor_sync(0xffffffffu, ls0, 2);
        ls1 += __shfl_xor_sync(0xffffffffu, ls1, 1);
        ls1 += __shfl_xor_sync(0xffffffffu, ls1, 2);
        l0r = l0r * al0 + ls0;
        l1r = l1r * al1 + ls1;
        m0r = mn0;
        m1r = mn1;
#pragma unroll
        for (int nd = 0; nd < 8; nd++) {
            o[nd][0] *= al0; o[nd][1] *= al0;
            o[nd][2] *= al1; o[nd][3] *= al1;
        }

#pragma unroll
        for (int ks = 0; ks < 4; ks++) {
            uint32_t pah[4];
#pragma unroll
            for (int u = 0; u < 2; u++) {
                pah[2 * u] = hpack(c[2 * ks + u][0], c[2 * ks + u][1]);
                pah[2 * u + 1] = hpack(c[2 * ks + u][2], c[2 * ks + u][3]);
            }
#pragma unroll
            for (int pd = 0; pd < 4; pd++) {
                uint32_t vb[4];
                LM4(vb, stg + 9216 +
                            (uint32_t)((pd * 16 + krow) * 144 + kcol * 2) +
                            ks * 32);
                mma16816(o[2 * pd], pah, vb);
                mma16816(o[2 * pd + 1], pah, vb + 2);
            }
        }
        __syncthreads();
    }

    const float i0 = 1.f / l0r, i1 = 1.f / l1r;
    const size_t row0 = (size_t)b * Tn + qbase + wm * 16 + lg;
    const size_t row1 = row0 + 8;
#pragma unroll
    for (int nd = 0; nd < 8; nd++) {
        int col = h * Dn + nd * 8 + 2 * lc;
        *(uint32_t*)&g_a[row0 * En + col] = hpack(o[nd][0] * i0, o[nd][1] * i0);
        *(uint32_t*)&g_a[row1 * En + col] = hpack(o[nd][2] * i1, o[nd][3] * i1);
    }
}

// ---------------------------------------------------------------------------
extern "C" void kernel_launch(void* const* d_in, const int* in_sizes, int n_in,
                              void* d_out, int out_size) {
    (void)in_sizes; (void)n_in; (void)out_size;
    const float* x = (const float*)d_in[0];
    const int* idsw = (const int*)d_in[1];
    const float* w_qkv = (const float*)d_in[2];
    const float* w_out = (const float*)d_in[3];
    const float* b_out = (const float*)d_in[4];
    float* out = (float*)d_out;

    // merged prep: x->fp16 + ids detect + weight transposes (one launch)
    prep_kernel<<<6144, 256>>>(x, w_qkv, w_out, idsw);

    const int gsmem = 2 * 27648;  // 55296 B -> 4 CTAs/SM
    cudaFuncSetAttribute(hmma_gemm<3 * En, true>,
                         cudaFuncAttributeMaxDynamicSharedMemorySize, gsmem);
    cudaFuncSetAttribute(hmma_gemm<En, false>,
                         cudaFuncAttributeMaxDynamicSharedMemorySize, gsmem);

    // 1) QKV projection -> q (pre-scaled), k ([bh][t][d]) + v^T ([bh][d][t])
    dim3 g1(3 * En / 64, Bn * Tn / 128);  // (48, 64)
    hmma_gemm<3 * En, true><<<g1, 128, gsmem>>>(nullptr, nullptr);

    // 2) flash attention (fp16 single) -> y fp16 into g_a
    cudaFuncSetAttribute(flash_kernel,
                         cudaFuncAttributeMaxDynamicSharedMemorySize, FLASH_SMEM);
    dim3 g2(Tn / 128, Bn * Hn);  // (16, 64)
    flash_kernel<<<g2, 256, FLASH_SMEM>>>(idsw);

    // 3) output projection + bias
    dim3 g3(En / 64, Bn * Tn / 128);  // (16, 64)
    hmma_gemm<En, false><<<g3, 128, gsmem>>>(b_out, out);
}